// round 6
// baseline (speedup 1.0000x reference)
#include <cuda_runtime.h>

// Problem shape (fixed by the dataset)
#define BATCH 8
#define CHANS 3
#define IMG_H 720
#define IMG_W 1280
#define EPS_F 1e-6f
// log2(1.414) in double precision
#define LOG2_WARP_BASE 0.49978212546913446f

#define NC 42                 // iterations per lane; lane stride 42 >= tap reach
#define STG 1312              // skewed staging array size (max used index 1309)

__device__ __forceinline__ float fast_exp2(float x) {
    float r; asm("ex2.approx.f32 %0, %1;" : "=f"(r) : "f"(x)); return r;
}

// One row per block (64 threads = 2 warps). Lane l owns columns 42*l + c.
// Tap windows of distinct lanes are disjoint for every c (stride 42 >= reach 42),
// and the two warps update disjoint bin arrays, so bin updates need NO atomics:
// plain LDS+FFMA+STS. Static smem = 46,592 B < 48 KB (no opt-in needed).
__global__ __launch_bounds__(64)
void warp_row_kernel(const float* __restrict__ im,
                     const float* __restrict__ disp,
                     float* __restrict__ out_res,
                     float* __restrict__ out_occ) {
    __shared__ float b0[IMG_W];
    __shared__ float b1[IMG_W];
    __shared__ float b2[IMG_W];
    __shared__ float bmw[IMG_W];
    __shared__ float bon[IMG_W];
    __shared__ float sd[STG];
    __shared__ float s0[STG];
    __shared__ float s1[STG];
    __shared__ float s2[STG];

    const int tid = threadIdx.x;          // 0..63
    const int warp = tid >> 5;
    const int lane = tid & 31;
    const int role = warp;                // 0: {b0,b1}, 1: {b2,bmw,bon}

    const int row = blockIdx.x;           // b*H + y
    const int b = row / IMG_H;
    const int y = row - b * IMG_H;

    const float* drow = disp + (size_t)row * IMG_W;
    const float* g0 = im + (((size_t)b * CHANS + 0) * IMG_H + y) * IMG_W;
    const float* g1 = im + (((size_t)b * CHANS + 1) * IMG_H + y) * IMG_W;
    const float* g2 = im + (((size_t)b * CHANS + 2) * IMG_H + y) * IMG_W;

    // Zero bins and stage the row into skewed smem (p = i + i/42 so the
    // stride-42 compute-phase accesses are bank-conflict-free).
    #pragma unroll
    for (int k = 0; k < IMG_W / 64; k++) {
        int i = tid + 64 * k;
        b0[i] = 0.0f; b1[i] = 0.0f; b2[i] = 0.0f; bmw[i] = 0.0f; bon[i] = 0.0f;
        int p = i + i / 42;
        sd[p] = drow[i];
        s0[p] = g0[i];
        s1[p] = g1[i];
        s2[p] = g2[i];
    }
    __syncthreads();

    // Main splat loop: lane l handles col = 42*l + c.
    for (int c = 0; c < NC; c++) {
        int col = 42 * lane + c;
        if (col < IMG_W) {
            int p = 43 * lane + c;                 // skewed staging index
            float d = sd[p];
            float wm = fast_exp2(d * (float)LOG2_WARP_BASE);
            float x = (float)col - d;
            float x0f = floorf(x);
            int xi = (int)x0f;
            int xj = xi + 1;
            float wx1 = x - x0f;
            float wx0 = 1.0f - wx1;
            bool oki = (xi >= 0);                  // xi <= col < W always
            bool okj = (xj >= 0) && (xj < IMG_W);
            if (role == 0) {
                float v0 = s0[p] * wm;
                float v1 = s1[p] * wm;
                if (oki) { b0[xi] += v0 * wx0; b1[xi] += v1 * wx0; }
                if (okj) { b0[xj] += v0 * wx1; b1[xj] += v1 * wx1; }
            } else {
                float v2 = s2[p] * wm;
                if (oki) { b2[xi] += v2 * wx0; bmw[xi] += wm * wx0; bon[xi] += wx0; }
                if (okj) { b2[xj] += v2 * wx1; bmw[xj] += wm * wx1; bon[xj] += wx1; }
            }
        }
    }
    __syncthreads();

    // Epilogue: normalize + occlusion, float4 loads/stores.
    float4* r0 = (float4*)(out_res + (((size_t)b * CHANS + 0) * IMG_H + y) * IMG_W);
    float4* r1 = (float4*)(out_res + (((size_t)b * CHANS + 1) * IMG_H + y) * IMG_W);
    float4* r2 = (float4*)(out_res + (((size_t)b * CHANS + 2) * IMG_H + y) * IMG_W);
    float4* oc = (float4*)(out_occ + (size_t)row * IMG_W);
    const float4* B0 = (const float4*)b0;
    const float4* B1 = (const float4*)b1;
    const float4* B2 = (const float4*)b2;
    const float4* BM = (const float4*)bmw;
    const float4* BO = (const float4*)bon;

    #pragma unroll
    for (int k = 0; k < (IMG_W / 4) / 64; k++) {
        int i = tid + 64 * k;
        float4 m4 = BM[i];
        float4 i0 = B0[i];
        float4 i1 = B1[i];
        float4 i2 = B2[i];
        float4 o4 = BO[i];
        float inx = 1.0f / fmaxf(m4.x, EPS_F);
        float iny = 1.0f / fmaxf(m4.y, EPS_F);
        float inz = 1.0f / fmaxf(m4.z, EPS_F);
        float inw = 1.0f / fmaxf(m4.w, EPS_F);
        r0[i] = make_float4(i0.x * inx, i0.y * iny, i0.z * inz, i0.w * inw);
        r1[i] = make_float4(i1.x * inx, i1.y * iny, i1.z * inz, i1.w * inw);
        r2[i] = make_float4(i2.x * inx, i2.y * iny, i2.z * inz, i2.w * inw);
        oc[i] = make_float4(1.0f - __saturatef(o4.x), 1.0f - __saturatef(o4.y),
                            1.0f - __saturatef(o4.z), 1.0f - __saturatef(o4.w));
    }
}

extern "C" void kernel_launch(void* const* d_in, const int* in_sizes, int n_in,
                              void* d_out, int out_size) {
    const float* im = (const float*)d_in[0];
    const float* disp = (const float*)d_in[1];
    float* out_res = (float*)d_out;
    float* out_occ = (float*)d_out + (size_t)BATCH * CHANS * IMG_H * IMG_W;

    warp_row_kernel<<<BATCH * IMG_H, 64>>>(im, disp, out_res, out_occ);
}